// round 8
// baseline (speedup 1.0000x reference)
#include <cuda_runtime.h>
#include <cuda_bf16.h>

// 16k -> 24k Kaldi polyphase resampler.
//   in_unit = 2, out_unit = 3, W = 13 taps, first_indices = {-6,-5,-4}
//   out[c, 3u+p] = sum_{j=0}^{12} x[c, 2u + (p-6) + j] * w[p][j]   (zero-padded)
//
// Design: 4 units (12 outputs) per thread, 2 groups of 256 threads
// -> 2048 units (6144 outputs) per CTA, one channel per blockIdx.y.
// Input segment staged in SMEM split into even/odd-float4 halves (8-float pad
// between) so both staging STS.128 and compute LDS.128 are bank-conflict-free.
// Staging uses unpredicated LDG.128 (g0 = 2*u0-8 is 16B-aligned). Stores are
// 3x STG.128 per thread-group (n0 = 3*u0 + 12*r is 16B-aligned).

#define RS_NT    256                       // threads per CTA
#define RS_G     2                         // groups per CTA
#define RS_UPT   4                         // units per thread per group
#define RS_UPB   (RS_NT * RS_G * RS_UPT)   // 2048 units per CTA
#define RS_SEGF  (2 * RS_UPB + 16)         // 4112 staged floats
#define RS_NF4   (RS_SEGF / 4)             // 1028 float4s
#define RS_A_LEN 2064                      // 516 float4s + 8-float bank pad
#define RS_B_LEN 2056                      // 514 float4s

__global__ __launch_bounds__(RS_NT, 3)
void resample_16k_24k_kernel(const float* __restrict__ x,
                             const float* __restrict__ w,
                             float* __restrict__ y,
                             int L, int tot)
{
    // Single allocation to pin the layout: [sA | sB | sw]
    __shared__ __align__(16) float smem[RS_A_LEN + RS_B_LEN + 40];
    float* sA = smem;                       // even float4s of the segment
    float* sB = smem + RS_A_LEN;            // odd  float4s (base 16 banks off sA)
    float* sw = smem + RS_A_LEN + RS_B_LEN; // 39 weights

    const int c  = blockIdx.y;
    const int u0 = blockIdx.x * RS_UPB;
    const float* xc = x + (size_t)c * (size_t)L;
    float*       yc = y + (size_t)c * (size_t)tot;

    if (threadIdx.x < 39) sw[threadIdx.x] = w[threadIdx.x];

    // Stage segment: logical s[i] = x[g0 + i], i in [0, RS_SEGF), zero outside
    // [0, L). float4 f of the segment -> (f even ? sA : sB)[f>>1].
    const int g0 = 2 * u0 - 8;                       // multiple of 4
    if (g0 >= 0 && g0 + RS_SEGF <= L) {
        const float4* xg = (const float4*)(xc + g0); // 16B-aligned
        #pragma unroll
        for (int k = 0; k < 4; k++) {
            const int f = k * RS_NT + threadIdx.x;
            const float4 v = __ldg(xg + f);
            float* dst = (f & 1) ? sB : sA;
            *(float4*)(dst + (f >> 1) * 4) = v;
        }
        if (threadIdx.x < RS_NF4 - 4 * RS_NT) {      // remainder: 4 float4s
            const int f = 4 * RS_NT + threadIdx.x;
            const float4 v = __ldg(xg + f);
            float* dst = (f & 1) ? sB : sA;
            *(float4*)(dst + (f >> 1) * 4) = v;
        }
    } else {
        // Edge CTAs (first/last per channel): scalar bounds-checked staging.
        for (int i = threadIdx.x; i < RS_SEGF; i += RS_NT) {
            const int g = g0 + i;
            const float v = (g >= 0 && g < L) ? __ldg(xc + g) : 0.0f;
            const int f = i >> 2;
            float* dst = (f & 1) ? sB : sA;
            dst[(f >> 1) * 4 + (i & 3)] = v;
        }
    }
    __syncthreads();

    // Weights to registers (39 broadcast LDS, uniform per thread).
    float wr[3][13];
    #pragma unroll
    for (int p = 0; p < 3; p++)
        #pragma unroll
        for (int j = 0; j < 13; j++)
            wr[p][j] = sw[p * 13 + j];

    #pragma unroll
    for (int gix = 0; gix < RS_G; gix++) {
        const int r = gix * RS_NT + threadIdx.x;     // thread work index
        // e[t] = s[8r + t], t = 0..23  (6 conflict-free LDS.128)
        const float4 va0 = *(const float4*)(sA + 4 * r);
        const float4 vb0 = *(const float4*)(sB + 4 * r);
        const float4 va1 = *(const float4*)(sA + 4 * (r + 1));
        const float4 vb1 = *(const float4*)(sB + 4 * (r + 1));
        const float4 va2 = *(const float4*)(sA + 4 * (r + 2));
        const float4 vb2 = *(const float4*)(sB + 4 * (r + 2));
        const float e[24] = {va0.x, va0.y, va0.z, va0.w,
                             vb0.x, vb0.y, vb0.z, vb0.w,
                             va1.x, va1.y, va1.z, va1.w,
                             vb1.x, vb1.y, vb1.z, vb1.w,
                             va2.x, va2.y, va2.z, va2.w,
                             vb2.x, vb2.y, vb2.z, vb2.w};

        // Units u0+4r+uu, phases p: out index n0 + 3*uu + p.
        // a[3uu+p] = sum_j e[2uu + p + 2 + j] * w[p][j]
        float a[12];
        #pragma unroll
        for (int p = 0; p < 3; p++) {
            #pragma unroll
            for (int uu = 0; uu < 4; uu++) {
                float acc = 0.0f;
                #pragma unroll
                for (int j = 0; j < 13; j++)
                    acc = fmaf(e[2 * uu + p + 2 + j], wr[p][j], acc);
                a[3 * uu + p] = acc;
            }
        }

        const int n0 = 3 * u0 + 12 * r;              // multiple of 4 -> STG.128
        if (n0 + 12 <= tot) {
            float4* yp = (float4*)(yc + n0);
            yp[0] = make_float4(a[0], a[1], a[2],  a[3]);
            yp[1] = make_float4(a[4], a[5], a[6],  a[7]);
            yp[2] = make_float4(a[8], a[9], a[10], a[11]);
        } else {
            #pragma unroll
            for (int k = 0; k < 12; k++)
                if (n0 + k < tot) yc[n0 + k] = a[k];
        }
    }
}

extern "C" void kernel_launch(void* const* d_in, const int* in_sizes, int n_in,
                              void* d_out, int out_size)
{
    // Inputs: waveform [8, L] float32, weights [3, 13] float32 (defensive
    // about ordering via element counts).
    int wav_i = 0, wts_i = 1;
    if (n_in >= 2 && in_sizes[0] < in_sizes[1]) { wav_i = 1; wts_i = 0; }

    const float* wav = (const float*)d_in[wav_i];
    const float* wts = (const float*)d_in[wts_i];
    float* out = (float*)d_out;

    const int C   = 8;
    const int L   = in_sizes[wav_i] / C;
    const int tot = out_size / C;                 // = 3L/2 = 6,000,000
    const int tot_units = (tot + 2) / 3;          // ceil(tot / 3)

    dim3 grid((tot_units + RS_UPB - 1) / RS_UPB, C);
    resample_16k_24k_kernel<<<grid, RS_NT>>>(wav, wts, out, L, tot);
}